// round 14
// baseline (speedup 1.0000x reference)
#include <cuda_runtime.h>
#include <cstdint>

// Problem constants
#define NUM_PROPERTIES 10000
#define HDIM 512
#define ODIM 2
#define BATCH 512
#define NUM_PROPS 128
#define NROWS (BATCH * NUM_PROPS)   // 65536 (b,p) rows

#define NSM 148
#define CTAS_PER_SM 8
#define GRID_CTAS (NSM * CTAS_PER_SM)            // 1184
#define WARPS_PER_CTA 8
#define TOTAL_WARPS (GRID_CTAS * WARPS_PER_CTA)  // 9472

// Cache-policy operand form (the textual .L2::evict_first qualifier is only
// legal on v8.b32 loads per ptxas on sm_103; the createpolicy + L2::cache_hint
// form works on any width and encodes the same descriptor).
__device__ __forceinline__ uint64_t make_evict_first_policy() {
    uint64_t pol;
    asm("createpolicy.fractional.L2::evict_first.b64 %0, 1.0;" : "=l"(pol));
    return pol;
}

// h stream load: L1::no_allocate (zero-reuse stream must not evict the W
// working set from L1) + L2 evict-first via policy (protects the 40 MiB W
// table's L2 residency -- the R2 win). Pure hints; correctness unaffected.
__device__ __forceinline__ float2 ld_stream_f2(const float2* p, uint64_t pol) {
    float2 v;
    asm volatile("ld.global.L1::no_allocate.L2::cache_hint.v2.f32 {%0,%1}, [%2], %3;"
                 : "=f"(v.x), "=f"(v.y) : "l"(p), "l"(pol));
    return v;
}

// Persistent grid-stride kernel; one warp per (b,p) row per iteration.
//
// Operating point (29.18us, reproduced 3x) with the full experiment bracket:
//   R1 baseline (8192-CTA, strided W loads)  35.3us
//   R2 +.cs streaming h/out                  33.5us  (DRAM bytes -> floor)
//   R3 +wavefront-minimal lane layout        31.2us  (L1 wf/row 80 -> 48)
//   R4 +persistent grid, fused detection     29.2us
//   R5 prop-prefetch pipeline                29.4us  (warp pool already hides)
//   R6 property-binned reorder               77.9us  (scatter cost >> reuse)
//   R7 full unroll @ 6 CTAs/SM               33.5us  (occupancy > per-warp MLP)
//   R9 fp16 W shadow (L2 bytes -33%)         41.5us  (bytes NOT binding)
// R13 change (= R12 intent, fixed encoding): h loads/out stores use
// L1::no_allocate + L2-evict-first policy. Per-SM W working set (64 warps x
// 4KB = 256KB) exceeds L1 (228KB); h L1 allocations were thrashing W.
//
// Dtype self-detection (properties may be int32 or int64 depending on JAX
// x64 config): every warp reads p64[lane] (first 256 bytes, in-bounds under
// both interpretations) and ballots whether all 32 values lie in
// [0, NUM_PROPERTIES). int32 data passing this requires 32 consecutive
// odd-index props to be zero (~1e-128). Deterministic, identical across warps.
//
// Memory layout per row (wavefront-minimal):
//   W row = 256 float4; lane handles j = lane + 32k, k = 0..7 (contiguous
//   warp-wide, 4 wavefronts/instr); h row = 256 float2 paired 1:1 with W
//   float4s (2 wavefronts/instr).
__global__ __launch_bounds__(256, CTAS_PER_SM)
void adapter_gemv_kernel(
    const float*  __restrict__ hs,     // (B, P, H)
    const int*    __restrict__ props,  // (B, P) int32 or int64 (detected)
    const float*  __restrict__ mask,   // (B, P)
    const float*  __restrict__ W,      // (NUM_PROPERTIES, H, 2)
    const float2* __restrict__ bias,   // (NUM_PROPERTIES, 2) viewed as float2
    float*        __restrict__ out)    // (B, P, 2)
{
    const int lane   = threadIdx.x & 31;
    const int gwarp0 = (blockIdx.x * blockDim.x + threadIdx.x) >> 5;
    const uint64_t pol = make_evict_first_policy();

    // --- per-warp dtype detection (one broadcast 256B window) ---
    const long long* p64 = (const long long*)props;
    long long probe = p64[lane];
    bool in_range = (probe >= 0) && (probe < NUM_PROPERTIES);
    const bool is64 = (__ballot_sync(0xffffffffu, in_range) == 0xffffffffu);

    for (int row = gwarp0; row < NROWS; row += TOTAL_WARPS) {
        long long prop;
        if (is64) prop = p64[row];
        else      prop = (long long)props[row];

        const float2* __restrict__ h2 = (const float2*)(hs + (size_t)row * HDIM);
        const float4* __restrict__ w4 = (const float4*)(W + (size_t)prop * (HDIM * ODIM));

        float acc0 = 0.0f, acc1 = 0.0f;
        #pragma unroll 4
        for (int k = 0; k < 8; k++) {
            const int j = lane + 32 * k;
            const float2 h = ld_stream_f2(&h2[j], pol);  // L1 bypass + L2 evict-first
            const float4 w = w4[j];                      // default: L1+L2 cached
            acc0 = fmaf(h.x, w.x, acc0);
            acc1 = fmaf(h.x, w.y, acc1);
            acc0 = fmaf(h.y, w.z, acc0);
            acc1 = fmaf(h.y, w.w, acc1);
        }

        #pragma unroll
        for (int off = 16; off > 0; off >>= 1) {
            acc0 += __shfl_xor_sync(0xffffffff, acc0, off);
            acc1 += __shfl_xor_sync(0xffffffff, acc1, off);
        }

        if (lane == 0) {
            const float  m = mask[row];
            const float2 b = bias[prop];   // one aligned 8B load
            float2 r;
            r.x = (acc0 + b.x) * m;
            r.y = (acc1 + b.y) * m;
            asm volatile("st.global.L1::no_allocate.L2::cache_hint.v2.f32 [%0], {%1,%2}, %3;"
                         :: "l"(((float2*)out) + row), "f"(r.x), "f"(r.y), "l"(pol));
        }
    }
}

extern "C" void kernel_launch(void* const* d_in, const int* in_sizes, int n_in,
                              void* d_out, int out_size) {
    const float*  hs    = (const float*)d_in[0];   // hidden_states (512,128,512) f32
    const int*    props = (const int*)d_in[1];     // properties (512,128)
    const float*  mask  = (const float*)d_in[2];   // mask (512,128) f32
    const float*  W     = (const float*)d_in[3];   // classifier_weights (10000,512,2) f32
    const float2* bias  = (const float2*)d_in[4];  // classifier_bias (10000,2) f32
    float*        out   = (float*)d_out;           // (512,128,2) f32

    adapter_gemv_kernel<<<GRID_CTAS, 256>>>(hs, props, mask, W, bias, out);
}

// round 15
// speedup vs baseline: 1.0122x; 1.0122x over previous
#include <cuda_runtime.h>
#include <cstdint>

// Problem constants
#define NUM_PROPERTIES 10000
#define HDIM 512
#define ODIM 2
#define BATCH 512
#define NUM_PROPS 128
#define NROWS (BATCH * NUM_PROPS)   // 65536 (b,p) rows

#define NSM 148
#define CTAS_PER_SM 8
#define GRID_CTAS (NSM * CTAS_PER_SM)            // 1184
#define WARPS_PER_CTA 8
#define TOTAL_WARPS (GRID_CTAS * WARPS_PER_CTA)  // 9472

// Cache-policy operand form (textual .L2::evict_first is v8-only on sm_103 ptxas).
__device__ __forceinline__ uint64_t make_evict_first_policy() {
    uint64_t pol;
    asm("createpolicy.fractional.L2::evict_first.b64 %0, 1.0;" : "=l"(pol));
    return pol;
}

// h stream load: L1::no_allocate + L2 evict-first (protects the 40 MiB W
// table's L2 residency). Pure hints; correctness unaffected.
__device__ __forceinline__ float2 ld_stream_f2(const float2* p, uint64_t pol) {
    float2 v;
    asm volatile("ld.global.L1::no_allocate.L2::cache_hint.v2.f32 {%0,%1}, [%2], %3;"
                 : "=f"(v.x), "=f"(v.y) : "l"(p), "l"(pol));
    return v;
}

// Persistent grid-stride kernel; one warp per (b,p) row per iteration.
//
// Operating point (29.18us, reproduced 4x). Full experiment bracket:
//   R1 baseline (8192-CTA, strided W loads)  35.3us
//   R2 +.cs streaming h/out                  33.5us  (DRAM bytes -> floor)
//   R3 +wavefront-minimal lane layout        31.2us  (L1 wf/row 80 -> 48)
//   R4 +persistent grid, fused detection     29.2us
//   R5 prop-prefetch pipeline                29.4us  (warp pool already hides)
//   R6 property-binned reorder               77.9us  (scatter cost >> reuse)
//   R7 full unroll @ 6 CTAs/SM               33.5us  (occupancy > per-warp MLP)
//   R9 fp16 W shadow (L2 bytes -33%)         41.5us  (bytes NOT binding)
//   R13 h L1-bypass                          29.2us  (neutral)
// R15 change: split warp reduction -- lanes 0-15 reduce acc0, lanes 16-31
// reduce acc1 (6 SHFLs instead of 10); lanes 0 and 16 each store one f32
// (adjacent -> one store wavefront). Last untouched per-row serial section.
//
// Dtype self-detection (properties may be int32 or int64 depending on JAX
// x64 config): every warp reads p64[lane] (first 256 bytes, in-bounds under
// both interpretations) and ballots whether all 32 values lie in
// [0, NUM_PROPERTIES). int32 data passing this requires 32 consecutive
// odd-index props to be zero (~1e-128). Deterministic, identical across warps.
//
// Memory layout per row (wavefront-minimal):
//   W row = 256 float4; lane handles j = lane + 32k, k = 0..7 (contiguous
//   warp-wide, 4 wavefronts/instr); h row = 256 float2 paired 1:1 with W
//   float4s (2 wavefronts/instr).
__global__ __launch_bounds__(256, CTAS_PER_SM)
void adapter_gemv_kernel(
    const float*  __restrict__ hs,     // (B, P, H)
    const int*    __restrict__ props,  // (B, P) int32 or int64 (detected)
    const float*  __restrict__ mask,   // (B, P)
    const float*  __restrict__ W,      // (NUM_PROPERTIES, H, 2)
    const float*  __restrict__ bias,   // (NUM_PROPERTIES, 2)
    float*        __restrict__ out)    // (B, P, 2)
{
    const int lane   = threadIdx.x & 31;
    const int gwarp0 = (blockIdx.x * blockDim.x + threadIdx.x) >> 5;
    const uint64_t pol = make_evict_first_policy();

    // --- per-warp dtype detection (one broadcast 256B window) ---
    const long long* p64 = (const long long*)props;
    long long probe = p64[lane];
    bool in_range = (probe >= 0) && (probe < NUM_PROPERTIES);
    const bool is64 = (__ballot_sync(0xffffffffu, in_range) == 0xffffffffu);

    const int half = lane >> 4;          // 0 for lanes 0-15, 1 for 16-31

    for (int row = gwarp0; row < NROWS; row += TOTAL_WARPS) {
        long long prop;
        if (is64) prop = p64[row];
        else      prop = (long long)props[row];

        const float2* __restrict__ h2 = (const float2*)(hs + (size_t)row * HDIM);
        const float4* __restrict__ w4 = (const float4*)(W + (size_t)prop * (HDIM * ODIM));

        float acc0 = 0.0f, acc1 = 0.0f;
        #pragma unroll 4
        for (int k = 0; k < 8; k++) {
            const int j = lane + 32 * k;
            const float2 h = ld_stream_f2(&h2[j], pol);  // L1 bypass + L2 evict-first
            const float4 w = w4[j];                      // default: L1+L2 cached
            acc0 = fmaf(h.x, w.x, acc0);
            acc1 = fmaf(h.x, w.y, acc1);
            acc0 = fmaf(h.y, w.z, acc0);
            acc1 = fmaf(h.y, w.w, acc1);
        }

        // Split reduction: cross-half exchange, then 16-lane tree per output.
        // Lanes 0-15 end with sum(acc0); lanes 16-31 with sum(acc1).
        const float o0 = __shfl_xor_sync(0xffffffffu, acc0, 16);
        const float o1 = __shfl_xor_sync(0xffffffffu, acc1, 16);
        float v = (half == 0) ? (acc0 + o0) : (acc1 + o1);
        #pragma unroll
        for (int off = 8; off > 0; off >>= 1)
            v += __shfl_xor_sync(0xffffffffu, v, off);

        if ((lane & 15) == 0) {          // lanes 0 and 16
            const float m  = mask[row];              // broadcast (same addr)
            const float bv = bias[prop * 2 + half];  // adjacent scalars
            const float r  = (v + bv) * m;
            asm volatile("st.global.cs.f32 [%0], %1;"
                         :: "l"(out + (size_t)row * 2 + half), "f"(r));
        }
    }
}

extern "C" void kernel_launch(void* const* d_in, const int* in_sizes, int n_in,
                              void* d_out, int out_size) {
    const float* hs    = (const float*)d_in[0];   // hidden_states (512,128,512) f32
    const int*   props = (const int*)d_in[1];     // properties (512,128)
    const float* mask  = (const float*)d_in[2];   // mask (512,128) f32
    const float* W     = (const float*)d_in[3];   // classifier_weights (10000,512,2) f32
    const float* bias  = (const float*)d_in[4];   // classifier_bias (10000,2) f32
    float*       out   = (float*)d_out;           // (512,128,2) f32

    adapter_gemv_kernel<<<GRID_CTAS, 256>>>(hs, props, mask, W, bias, out);
}